// round 1
// baseline (speedup 1.0000x reference)
#include <cuda_runtime.h>
#include <cstdint>

#define BB 8
#define NN 16384
#define CC 80
#define TT 100
#define CAND_CAP 2048

// ---------------- scratch (static device globals; no allocation) ----------------
__device__ float g_scores_t[(size_t)BB * CC * NN];          // 40 MB: scores transposed (B,C,N)
__device__ float g_det_scores[BB * CC * TT];                // per-class accepted scores (desc order)
__device__ float g_det_boxes[BB * CC * TT * 4];             // per-class accepted boxes
__device__ int   g_det_cnt[BB * CC];                        // per-class accepted count

// ---------------- kernel 0: transpose scores (B,N,C) -> (B,C,N) ----------------
__global__ void transpose_scores_kernel(const float* __restrict__ scores) {
    __shared__ float tile[32][33];
    const int b  = blockIdx.z;
    const int n0 = blockIdx.x * 32;
    const int c0 = blockIdx.y * 32;
    const int tx = threadIdx.x, ty = threadIdx.y;   // block (32,8)

    #pragma unroll
    for (int j = 0; j < 32; j += 8) {
        int n = n0 + ty + j;
        int c = c0 + tx;
        if (c < CC)
            tile[ty + j][tx] = scores[((size_t)b * NN + n) * CC + c];
    }
    __syncthreads();
    #pragma unroll
    for (int j = 0; j < 32; j += 8) {
        int c = c0 + ty + j;
        int n = n0 + tx;
        if (c < CC)
            g_scores_t[((size_t)b * CC + c) * NN + n] = tile[tx][ty + j];
    }
}

// ---------------- kernel 1: per (b,c) greedy NMS ----------------
// Equivalence with the reference scan: argmax-with-suppression == process candidates
// in descending score order (ties: lower index first), accept iff IoU<0.5 vs all
// previously accepted. Bands partition (0.3, inf) so global descending order holds.
__global__ __launch_bounds__(256) void nms_kernel(const float* __restrict__ boxes) {
    const int c = blockIdx.x;
    const int b = blockIdx.y;
    const int tid = threadIdx.x;

    __shared__ unsigned long long keys[CAND_CAP];
    __shared__ float acc_y1[TT], acc_x1[TT], acc_y2[TT], acc_x2[TT];
    __shared__ float acc_s[TT], acc_area[TT];
    __shared__ int s_cnt, s_accept;

    if (tid == 0) s_accept = 0;
    __syncthreads();

    const float* sc_ptr = g_scores_t + ((size_t)b * CC + c) * NN;

    for (int band = 0; band < 14; ++band) {
        if (s_accept >= TT) break;

        const float lo = 0.95f - 0.05f * (float)band;            // band 13 -> lo = 0.30
        const float hi = (band == 0) ? 1e30f : (0.95f - 0.05f * (float)(band - 1));

        // --- filter this score band into the candidate buffer ---
        if (tid == 0) s_cnt = 0;
        __syncthreads();
        for (int n = tid; n < NN; n += 256) {
            float s = sc_ptr[n];
            bool in = (band < 13) ? (s >= lo && s < hi)
                                  : (s > 0.3f && s < hi);        // strict >, matches reference
            if (in) {
                int p = atomicAdd(&s_cnt, 1);
                if (p < CAND_CAP) {
                    unsigned long long k =
                        (((unsigned long long)(0xFFFFFFFFu - __float_as_uint(s))) << 32)
                        | (unsigned)n;
                    keys[p] = k;
                }
            }
        }
        __syncthreads();
        int cnt = s_cnt;
        if (cnt > CAND_CAP) cnt = CAND_CAP;
        if (cnt == 0) continue;

        // --- pad to pow2 and bitonic sort ascending (=> score desc, idx asc) ---
        int m = 1;
        while (m < cnt) m <<= 1;
        for (int i = cnt + tid; i < m; i += 256) keys[i] = 0xFFFFFFFFFFFFFFFFull;
        __syncthreads();
        for (int k = 2; k <= m; k <<= 1) {
            for (int j = k >> 1; j > 0; j >>= 1) {
                for (int i = tid; i < m; i += 256) {
                    int ixj = i ^ j;
                    if (ixj > i) {
                        bool up = ((i & k) == 0);
                        unsigned long long a = keys[i], bb2 = keys[ixj];
                        if ((a > bb2) == up) { keys[i] = bb2; keys[ixj] = a; }
                    }
                }
                __syncthreads();
            }
        }

        // --- serial greedy scan by warp 0; lanes parallelize accepted-box checks ---
        if (tid < 32) {
            int lane = tid;
            int k = s_accept;
            for (int i = 0; i < cnt && k < TT; ++i) {
                unsigned long long key = keys[i];
                int n = (int)(key & 0xFFFFFFFFu);
                float sc = __uint_as_float(0xFFFFFFFFu - (unsigned)(key >> 32));
                float4 bx = __ldg(((const float4*)boxes) + ((size_t)b * NN + n));
                float areaX = fmaxf(bx.z - bx.x, 0.0f) * fmaxf(bx.w - bx.y, 0.0f);
                bool sup = false;
                for (int j = lane; j < k; j += 32) {
                    float yy1 = fmaxf(bx.x, acc_y1[j]);
                    float xx1 = fmaxf(bx.y, acc_x1[j]);
                    float yy2 = fminf(bx.z, acc_y2[j]);
                    float xx2 = fminf(bx.w, acc_x2[j]);
                    float inter = fmaxf(yy2 - yy1, 0.0f) * fmaxf(xx2 - xx1, 0.0f);
                    float uni = fmaxf(acc_area[j] + areaX - inter, 1e-9f);
                    if (inter / uni >= 0.5f) sup = true;
                }
                if (!__any_sync(0xFFFFFFFFu, sup)) {
                    if (lane == 0) {
                        acc_y1[k] = bx.x; acc_x1[k] = bx.y;
                        acc_y2[k] = bx.z; acc_x2[k] = bx.w;
                        acc_s[k]  = sc;   acc_area[k] = areaX;
                    }
                    k++;
                    __syncwarp();
                }
            }
            if (lane == 0) s_accept = k;
            __syncwarp();
        }
        __syncthreads();
    }

    // --- write per-class results to scratch ---
    int k = s_accept;
    int base = (b * CC + c) * TT;
    if (tid == 0) g_det_cnt[b * CC + c] = k;
    for (int t = tid; t < k; t += 256) {
        g_det_scores[base + t] = acc_s[t];
        g_det_boxes[(base + t) * 4 + 0] = acc_y1[t];
        g_det_boxes[(base + t) * 4 + 1] = acc_x1[t];
        g_det_boxes[(base + t) * 4 + 2] = acc_y2[t];
        g_det_boxes[(base + t) * 4 + 3] = acc_x2[t];
    }
}

// ---------------- kernel Z: clear output (it is poisoned) ----------------
__global__ void zero_out_kernel(float* out, int out_size) {
    int i = blockIdx.x * blockDim.x + threadIdx.x;
    if (i < out_size) out[i] = 0.0f;
}

// ---------------- kernel 2: per-batch top-100 merge over 80 sorted lists --------
// Ties broken by lower flat index (c*100+slot), matching jax.lax.top_k.
__global__ void merge_topk_kernel(float* __restrict__ out, int out_size) {
    const int b = blockIdx.x;
    const int tid = threadIdx.x;        // 128 threads
    __shared__ int head[CC];
    __shared__ unsigned long long red[128];
    __shared__ int s_winner;            // packed (c<<16)|slot, or -1

    if (tid < CC) head[tid] = 0;
    __syncthreads();

    int nvalid = 0;
    const int OB = 0;                       // boxes: B*100*4 = 3200
    const int OS = BB * TT * 4;             // scores: 3200..3999
    const int OL = OS + BB * TT;            // labels: 4000..4799
    const int OV = OL + BB * TT;            // valid:  4800..4807

    for (int t = 0; t < TT; ++t) {
        unsigned long long key = 0ull;
        if (tid < CC) {
            int h = head[tid];
            if (h < g_det_cnt[b * CC + tid]) {
                float s = g_det_scores[(b * CC + tid) * TT + h];
                unsigned fi = (unsigned)(tid * TT + h);
                key = (((unsigned long long)__float_as_uint(s)) << 32)
                      | (0xFFFFFFFFu - fi);
            }
        }
        red[tid] = key;
        __syncthreads();
        for (int off = 64; off > 0; off >>= 1) {
            if (tid < off) {
                unsigned long long o = red[tid + off];
                if (o > red[tid]) red[tid] = o;
            }
            __syncthreads();
        }
        unsigned long long w = red[0];

        if (tid == 0) {
            if (w != 0ull) {
                unsigned fi = 0xFFFFFFFFu - (unsigned)(w & 0xFFFFFFFFu);
                int c = (int)(fi / TT);
                int h = (int)(fi % TT);
                s_winner = (c << 16) | h;
                head[c] = h + 1;
                nvalid++;
            } else {
                s_winner = -1;
            }
        }
        __syncthreads();
        int win = s_winner;

        if (win >= 0) {
            int c = win >> 16, h = win & 0xFFFF;
            int base = (b * CC + c) * TT + h;
            if (tid == 0) {
                int si = OS + b * TT + t;
                int li = OL + b * TT + t;
                if (si < out_size) out[si] = g_det_scores[base];
                if (li < out_size) out[li] = (float)c;
            }
            if (tid < 4) {
                int bi = OB + (b * TT + t) * 4 + tid;
                if (bi < out_size) out[bi] = g_det_boxes[base * 4 + tid];
            }
        }
        // invalid slots: buffer already zeroed
        __syncthreads();
    }
    if (tid == 0) {
        int vi = OV + b;
        if (vi < out_size) out[vi] = (float)nvalid;
    }
}

// ---------------- launch ----------------
extern "C" void kernel_launch(void* const* d_in, const int* in_sizes, int n_in,
                              void* d_out, int out_size) {
    const float* boxes  = (const float*)d_in[0];
    const float* scores = (const float*)d_in[1];
    // safety: identify by size (boxes = B*N*4, scores = B*N*C)
    if (n_in >= 2 && in_sizes[0] > in_sizes[1]) {
        const float* tmp = boxes; boxes = scores; scores = tmp;
    }
    float* out = (float*)d_out;

    transpose_scores_kernel<<<dim3(NN / 32, (CC + 31) / 32, BB), dim3(32, 8)>>>(scores);
    nms_kernel<<<dim3(CC, BB), 256>>>(boxes);
    zero_out_kernel<<<(out_size + 255) / 256, 256>>>(out, out_size);
    merge_topk_kernel<<<BB, 128>>>(out, out_size);
}